// round 1
// baseline (speedup 1.0000x reference)
#include <cuda_runtime.h>
#include <cuda_bf16.h>

// Yolov1 loss, fused single pass.
// B=16384, S0=S1=7, NB=2, NC=20, D=30. Cells = 802816 = 3136 blocks * 256 threads.
//
// Layout per cell (30 contiguous floats):
//   [0:2)   conf logits (NB=2)
//   [2:10)  box logits, (NB,4): pb[nb][k] = p[2 + nb*4 + k]
//   [10:30) class logits (NC=20)

#define NBLOCKS 3136
#define NTHREADS 256

__device__ float g_partials[NBLOCKS];

__device__ __forceinline__ float fsig(float x) {
    return __fdividef(1.0f, 1.0f + __expf(-x));
}

__global__ __launch_bounds__(NTHREADS)
void yolo_loss_kernel(const float* __restrict__ pred,
                      const int*   __restrict__ grid,
                      const float* __restrict__ tbox,
                      const int*   __restrict__ tcls)
{
    // Stage 256 cells * 30 floats = 30720 B via coalesced float4 loads.
    __shared__ float sp[NTHREADS * 30];
    {
        const float4* src = reinterpret_cast<const float4*>(pred)
                          + (size_t)blockIdx.x * (NTHREADS * 30 / 4);   // 1920 float4/block
        float4* dst = reinterpret_cast<float4*>(sp);
        #pragma unroll
        for (int i = 0; i < 8; i++) {
            int idx = threadIdx.x + i * NTHREADS;
            if (idx < NTHREADS * 30 / 4) dst[idx] = src[idx];
        }
    }
    __syncthreads();

    const int t = blockIdx.x * NTHREADS + threadIdx.x;   // global cell index
    const float* p = sp + threadIdx.x * 30;

    // cell coords: s = t % 49, row s0 = s/7, col s1 = s%7
    const int s = t % 49;
    const float xg = (float)(s % 7);   // column
    const float yg = (float)(s / 7);   // row
    const float inv7 = 1.0f / 7.0f;

    const int   g  = grid[t];
    const float4 tb = reinterpret_cast<const float4*>(tbox)[t];
    const int   tc = tcls[t];
    const float tox = tb.x, toy = tb.y, tw = tb.z, th = tb.w;

    // sigmoids
    const float conf0 = fsig(p[0]);
    const float conf1 = fsig(p[1]);
    float pb[2][4];
    #pragma unroll
    for (int nb = 0; nb < 2; nb++)
        #pragma unroll
        for (int k = 0; k < 4; k++)
            pb[nb][k] = fsig(p[2 + nb * 4 + k]);

    // softmax class prob at target class (no max-shift needed: |logit| small)
    float esum = 0.0f, et = 0.0f;
    #pragma unroll
    for (int j = 0; j < 20; j++) {
        const float e = __expf(p[10 + j]);
        esum += e;
        if (j == tc) et = e;
    }
    const float cls_t = __fdividef(et, esum);

    // IOU of each predicted box vs the target box
    const float tcx = (xg + tox) * inv7;
    const float tcy = (yg + toy) * inv7;
    float iou[2];
    #pragma unroll
    for (int nb = 0; nb < 2; nb++) {
        const float pcx = (xg + pb[nb][0]) * inv7;
        const float pcy = (yg + pb[nb][1]) * inv7;
        const float pw = pb[nb][2], ph = pb[nb][3];
        const float tb_ = fminf(tcx + tw * 0.5f, pcx + pw * 0.5f)
                        - fmaxf(tcx - tw * 0.5f, pcx - pw * 0.5f);
        const float lr_ = fminf(tcy + th * 0.5f, pcy + ph * 0.5f)
                        - fmaxf(tcy - th * 0.5f, pcy - ph * 0.5f);
        const float inter = (tb_ < 0.0f || lr_ < 0.0f) ? 0.0f : tb_ * lr_;
        iou[nb] = __fdividef(inter, tw * th + pw * ph - inter);
    }

    // best predictor: first max index on tie (argmax semantics)
    const int best = (iou[1] > iou[0]) ? 1 : 0;
    const float iou_b  = iou[best];
    const float conf_b = best ? conf1 : conf0;
    const float b0 = pb[best][0], b1 = pb[best][1], b2 = pb[best][2], b3 = pb[best][3];

    const float d0 = b0 - tox;
    const float d1 = b1 - toy;
    const float d2 = __fsqrt_rn(b2) - __fsqrt_rn(tw);
    const float d3 = __fsqrt_rn(b3) - __fsqrt_rn(th);
    const float coord = d0 * d0 + d1 * d1 + d2 * d2 + d3 * d3;

    const float dc = conf_b - iou_b;
    const float dl = 1.0f - cls_t;
    const float obj_loss   = 5.0f * coord + dc * dc + dl * dl;
    const float noobj_loss = 0.5f * (conf0 * conf0 + conf1 * conf1);

    float v = (g == 1) ? obj_loss : noobj_loss;

    // block reduction -> g_partials[blockIdx.x]
    #pragma unroll
    for (int o = 16; o; o >>= 1) v += __shfl_down_sync(0xffffffffu, v, o);
    __shared__ float wsum[NTHREADS / 32];
    if ((threadIdx.x & 31) == 0) wsum[threadIdx.x >> 5] = v;
    __syncthreads();
    if (threadIdx.x < NTHREADS / 32) {
        v = wsum[threadIdx.x];
        #pragma unroll
        for (int o = NTHREADS / 64; o; o >>= 1) v += __shfl_down_sync(0xffu, v, o);
        if (threadIdx.x == 0) g_partials[blockIdx.x] = v;
    }
}

__global__ __launch_bounds__(256)
void yolo_reduce_kernel(float* __restrict__ out)
{
    double v = 0.0;
    for (int i = threadIdx.x; i < NBLOCKS; i += 256) v += (double)g_partials[i];
    #pragma unroll
    for (int o = 16; o; o >>= 1) v += __shfl_down_sync(0xffffffffu, v, o);
    __shared__ double ws[8];
    if ((threadIdx.x & 31) == 0) ws[threadIdx.x >> 5] = v;
    __syncthreads();
    if (threadIdx.x == 0) {
        double sum = 0.0;
        #pragma unroll
        for (int i = 0; i < 8; i++) sum += ws[i];
        out[0] = (float)(sum / 16384.0);
    }
}

extern "C" void kernel_launch(void* const* d_in, const int* in_sizes, int n_in,
                              void* d_out, int out_size)
{
    const float* pred = (const float*)d_in[0];   // (B, 1470) f32
    const int*   grid = (const int*)  d_in[1];   // (B, 7, 7) i32
    const float* tbox = (const float*)d_in[2];   // (B, 7, 7, 4) f32
    const int*   tcls = (const int*)  d_in[3];   // (B, 7, 7) i32
    float* out = (float*)d_out;

    yolo_loss_kernel<<<NBLOCKS, NTHREADS>>>(pred, grid, tbox, tcls);
    yolo_reduce_kernel<<<1, 256>>>(out);
}

// round 3
// speedup vs baseline: 1.0018x; 1.0018x over previous
#include <cuda_runtime.h>
#include <cuda_bf16.h>

// Yolov1 loss, fused single pass + last-block-done final reduction.
// B=16384, S0=S1=7, NB=2, NC=20, D=30. Cells = 802816 = 3136 blocks * 256 threads.
//
// Layout per cell (30 contiguous floats):
//   [0:2)   conf logits (NB=2)
//   [2:10)  box logits, (NB,4): pb[nb][k] = p[2 + nb*4 + k]
//   [10:30) class logits (NC=20)

#define NBLOCKS 3136
#define NTHREADS 256

__device__ float g_partials[NBLOCKS];
__device__ unsigned int g_done = 0;   // atomicInc mod NBLOCKS -> self-resetting

__device__ __forceinline__ float fsig(float x) {
    return __fdividef(1.0f, 1.0f + __expf(-x));
}

__global__ __launch_bounds__(NTHREADS)
void yolo_loss_kernel(const float* __restrict__ pred,
                      const int*   __restrict__ grid,
                      const float* __restrict__ tbox,
                      const int*   __restrict__ tcls,
                      float* __restrict__ out)
{
    // Stage 256 cells * 30 floats = 30720 B via coalesced float4 loads.
    __shared__ float sp[NTHREADS * 30];
    {
        const float4* src = reinterpret_cast<const float4*>(pred)
                          + (size_t)blockIdx.x * (NTHREADS * 30 / 4);   // 1920 float4/block
        float4* dst = reinterpret_cast<float4*>(sp);
        #pragma unroll
        for (int i = 0; i < 8; i++) {
            int idx = threadIdx.x + i * NTHREADS;
            if (idx < NTHREADS * 30 / 4) dst[idx] = src[idx];
        }
    }
    __syncthreads();

    const int t = blockIdx.x * NTHREADS + threadIdx.x;   // global cell index
    const float* p = sp + threadIdx.x * 30;

    // cell coords: s = t % 49, row s0 = s/7, col s1 = s%7
    const int s = t % 49;
    const float xg = (float)(s % 7);   // column
    const float yg = (float)(s / 7);   // row
    const float inv7 = 1.0f / 7.0f;

    const int   g  = grid[t];
    const float4 tb = reinterpret_cast<const float4*>(tbox)[t];
    const int   tc = tcls[t];
    const float tox = tb.x, toy = tb.y, tw = tb.z, th = tb.w;

    // sigmoids
    const float conf0 = fsig(p[0]);
    const float conf1 = fsig(p[1]);
    float pb[2][4];
    #pragma unroll
    for (int nb = 0; nb < 2; nb++)
        #pragma unroll
        for (int k = 0; k < 4; k++)
            pb[nb][k] = fsig(p[2 + nb * 4 + k]);

    // softmax class prob at target class (no max-shift needed: |logit| small)
    float esum = 0.0f, et = 0.0f;
    #pragma unroll
    for (int j = 0; j < 20; j++) {
        const float e = __expf(p[10 + j]);
        esum += e;
        if (j == tc) et = e;
    }
    const float cls_t = __fdividef(et, esum);

    // IOU of each predicted box vs the target box
    const float tcx = (xg + tox) * inv7;
    const float tcy = (yg + toy) * inv7;
    float iou[2];
    #pragma unroll
    for (int nb = 0; nb < 2; nb++) {
        const float pcx = (xg + pb[nb][0]) * inv7;
        const float pcy = (yg + pb[nb][1]) * inv7;
        const float pw = pb[nb][2], ph = pb[nb][3];
        const float tb_ = fminf(tcx + tw * 0.5f, pcx + pw * 0.5f)
                        - fmaxf(tcx - tw * 0.5f, pcx - pw * 0.5f);
        const float lr_ = fminf(tcy + th * 0.5f, pcy + ph * 0.5f)
                        - fmaxf(tcy - th * 0.5f, pcy - ph * 0.5f);
        const float inter = (tb_ < 0.0f || lr_ < 0.0f) ? 0.0f : tb_ * lr_;
        iou[nb] = __fdividef(inter, tw * th + pw * ph - inter);
    }

    // best predictor: first max index on tie (argmax semantics)
    const int best = (iou[1] > iou[0]) ? 1 : 0;
    const float iou_b  = iou[best];
    const float conf_b = best ? conf1 : conf0;
    const float b0 = pb[best][0], b1 = pb[best][1], b2 = pb[best][2], b3 = pb[best][3];

    const float d0 = b0 - tox;
    const float d1 = b1 - toy;
    const float d2 = __fsqrt_rn(b2) - __fsqrt_rn(tw);
    const float d3 = __fsqrt_rn(b3) - __fsqrt_rn(th);
    const float coord = d0 * d0 + d1 * d1 + d2 * d2 + d3 * d3;

    const float dc = conf_b - iou_b;
    const float dl = 1.0f - cls_t;
    const float obj_loss   = 5.0f * coord + dc * dc + dl * dl;
    const float noobj_loss = 0.5f * (conf0 * conf0 + conf1 * conf1);

    float v = (g == 1) ? obj_loss : noobj_loss;

    // block reduction -> g_partials[blockIdx.x]
    #pragma unroll
    for (int o = 16; o; o >>= 1) v += __shfl_down_sync(0xffffffffu, v, o);
    __shared__ float wsum[NTHREADS / 32];
    __shared__ bool s_last;
    if ((threadIdx.x & 31) == 0) wsum[threadIdx.x >> 5] = v;
    __syncthreads();
    if (threadIdx.x < NTHREADS / 32) {
        v = wsum[threadIdx.x];
        #pragma unroll
        for (int o = NTHREADS / 64; o; o >>= 1) v += __shfl_down_sync(0xffu, v, o);
        if (threadIdx.x == 0) {
            g_partials[blockIdx.x] = v;
            __threadfence();
            // atomicInc wraps to 0 after NBLOCKS arrivals -> self-resetting
            unsigned int prev = atomicInc(&g_done, NBLOCKS - 1);
            s_last = (prev == NBLOCKS - 1);
        }
    }
    __syncthreads();

    // Last-arriving block performs the final reduction (fixed order -> deterministic)
    if (s_last) {
        double acc = 0.0;
        for (int i = threadIdx.x; i < NBLOCKS; i += NTHREADS)
            acc += (double)g_partials[i];
        #pragma unroll
        for (int o = 16; o; o >>= 1) acc += __shfl_down_sync(0xffffffffu, acc, o);
        __shared__ double ws[NTHREADS / 32];
        if ((threadIdx.x & 31) == 0) ws[threadIdx.x >> 5] = acc;
        __syncthreads();
        if (threadIdx.x == 0) {
            double sum = 0.0;
            #pragma unroll
            for (int i = 0; i < NTHREADS / 32; i++) sum += ws[i];
            out[0] = (float)(sum / 16384.0);
        }
    }
}

extern "C" void kernel_launch(void* const* d_in, const int* in_sizes, int n_in,
                              void* d_out, int out_size)
{
    const float* pred = (const float*)d_in[0];   // (B, 1470) f32
    const int*   grid = (const int*)  d_in[1];   // (B, 7, 7) i32
    const float* tbox = (const float*)d_in[2];   // (B, 7, 7, 4) f32
    const int*   tcls = (const int*)  d_in[3];   // (B, 7, 7) i32
    float* out = (float*)d_out;

    yolo_loss_kernel<<<NBLOCKS, NTHREADS>>>(pred, grid, tbox, tcls, out);
}